// round 7
// baseline (speedup 1.0000x reference)
#include <cuda_runtime.h>
#include <cstdint>

#define NB 16
#define TN 8
#define CC 1024
#define NH 16
#define HD 64
#define TP 4096
#define TF 4104
#define NROWS 128          // NB*TN
#define CH 64              // keys per chunk
#define NCHUNK 64          // past chunks; chunk index NCHUNK is the 8-key tail

#define OUT_K_OFF  131072              // floats
#define KV_ELEMS   67239936            // 256*4104*64
#define OUT_V_OFF  (OUT_K_OFF + KV_ELEMS)

// attention dynamic smem layout (floats)
#define SM_KS   0                      // 2 bufs * 64 keys * 16 float4 = 8192 floats
#define SM_VS   8192                   // 8192 floats
#define SM_QS   16384                  // 512
#define SM_SP   16896                  // 4*8*64 = 2048 (score partials)
#define SM_PB   18944                  // 8*64 = 512 (probabilities)
#define SM_AL   19456                  // 8 (alpha per query)
#define SM_LS   19464                  // 8 (l per query)
#define SM_YT   19472                  // 512 (y reduction)
#define SM_FLOATS 19984
#define SMEM_BYTES (SM_FLOATS * 4)     // 79936 B

// scratch (allocation-free rule: __device__ globals)
__device__ __align__(16) float g_q[NB * NH * TN * HD];   // scaled q, [b][h][t][d]
__device__ __align__(16) float g_y[NROWS * CC];          // attention out, (B,T,C)

// ---------------------------------------------------------------------------
// GEMM: out[row][n] = sum_k X[row][k] * W[n][k] + bias[n], rows = 128.
// Block covers a 16-column slab of W across all 128 rows. 256 threads:
// thread -> (n = n0 + (tid&15), rows rg*8 .. rg*8+7), rg = tid>>4.
// MODE 0: QKV (X = x input, N=3072) -> scatter q/k_new/v_new
// MODE 1: proj (X = g_y,     N=1024) -> out
// ---------------------------------------------------------------------------
template <int MODE>
__global__ __launch_bounds__(256) void gemm_kernel(
    const float* __restrict__ Xin, const float* __restrict__ W,
    const float* __restrict__ bias, float* __restrict__ out,
    float* __restrict__ outk, float* __restrict__ outv)
{
    __shared__ float xs[128 * 68];
    __shared__ float ws[16 * 68];

    const float* X = (MODE == 0) ? Xin : (const float*)g_y;

    const int tid = threadIdx.x;
    const int n0  = blockIdx.x * 16;
    const int nl  = tid & 15;
    const int rg  = tid >> 4;

    float acc[8];
#pragma unroll
    for (int r = 0; r < 8; r++) acc[r] = 0.f;

    for (int kt = 0; kt < CC; kt += 64) {
        // load X tile: 128 rows x 64 k = 2048 float4
#pragma unroll
        for (int i = 0; i < 8; i++) {
            int fi = tid + i * 256;
            int row = fi >> 4, k4 = fi & 15;
            float4 v = *(const float4*)&X[(size_t)row * CC + kt + k4 * 4];
            *(float4*)&xs[row * 68 + k4 * 4] = v;
        }
        // load W tile: 16 n x 64 k = 256 float4
        {
            int n = tid >> 4, k4 = tid & 15;
            float4 v = *(const float4*)&W[(size_t)(n0 + n) * CC + kt + k4 * 4];
            *(float4*)&ws[n * 68 + k4 * 4] = v;
        }
        __syncthreads();

#pragma unroll
        for (int k4 = 0; k4 < 16; k4++) {
            float w0 = ws[nl * 68 + k4 * 4 + 0];
            float w1 = ws[nl * 68 + k4 * 4 + 1];
            float w2 = ws[nl * 68 + k4 * 4 + 2];
            float w3 = ws[nl * 68 + k4 * 4 + 3];
#pragma unroll
            for (int r = 0; r < 8; r++) {
                float4 xv = *(const float4*)&xs[(rg * 8 + r) * 68 + k4 * 4];
                acc[r] += xv.x * w0 + xv.y * w1 + xv.z * w2 + xv.w * w3;
            }
        }
        __syncthreads();
    }

    const int n = n0 + nl;
    const float bv = bias[n];
#pragma unroll
    for (int r = 0; r < 8; r++) {
        int row = rg * 8 + r;
        float val = acc[r] + bv;
        if (MODE == 0) {
            int b = row >> 3, t = row & 7;
            int d = n & 63;
            if (n < 1024) {
                int h = n >> 6;
                g_q[((b * NH + h) * TN + t) * HD + d] = val * 0.125f;  // fold 1/sqrt(hd)
            } else if (n < 2048) {
                int h = (n - 1024) >> 6;
                outk[((size_t)(b * NH + h) * TF + TP + t) * HD + d] = val;
            } else {
                int h = (n - 2048) >> 6;
                outv[((size_t)(b * NH + h) * TF + TP + t) * HD + d] = val;
            }
        } else {
            out[(size_t)row * CC + n] = val;
        }
    }
}

// ---------------------------------------------------------------------------
// cp.async helpers
// ---------------------------------------------------------------------------
__device__ __forceinline__ void cpa16(void* dst, const void* src) {
    uint32_t d = (uint32_t)__cvta_generic_to_shared(dst);
    asm volatile("cp.async.cg.shared.global [%0], [%1], 16;\n" ::"r"(d), "l"(src));
}

// ---------------------------------------------------------------------------
// Fused KV-cache copy + causal attention. grid = B*H, 256 threads.
// Streams past K/V through smem (double-buffered cp.async); each chunk is
// copied to out_k/out_v AND consumed by online-softmax attention (past K/V
// touched exactly once in HBM). Tail chunk (8 new keys) is read back from the
// out tails written by the QKV GEMM.
// ---------------------------------------------------------------------------
__global__ __launch_bounds__(256, 2) void attn_kernel(
    const float* __restrict__ pk, const float* __restrict__ pv,
    float* __restrict__ outk, float* __restrict__ outv)
{
    extern __shared__ float sm[];
    float4* ks4 = (float4*)(sm + SM_KS);
    float4* vs4 = (float4*)(sm + SM_VS);
    float*  qs  = sm + SM_QS;
    float*  sp  = sm + SM_SP;
    float*  pb  = sm + SM_PB;
    float*  al  = sm + SM_AL;
    float*  ls  = sm + SM_LS;
    float*  yt  = sm + SM_YT;

    const int tid  = threadIdx.x;
    const int w    = tid >> 5, lane = tid & 31;
    const int bh   = blockIdx.x;

    const float* pkb = pk + (size_t)bh * TP * HD;
    const float* pvb = pv + (size_t)bh * TP * HD;
    float* okb = outk + (size_t)bh * TF * HD;
    float* ovb = outv + (size_t)bh * TF * HD;

    if (tid < 128) {
        ((float4*)qs)[tid] = ((const float4*)g_q)[bh * 128 + tid];
        ((float4*)yt)[tid] = make_float4(0.f, 0.f, 0.f, 0.f);
    }

    // score mapping: thread -> (key, d-segment of 16)
    const int key  = (w & 1) * 32 + lane;
    const int dseg = w >> 1;

    // PV: warp w owns keys j = w*8 .. w*8+7; lane owns d = 2*lane, 2*lane+1
    float y[8][2];
#pragma unroll
    for (int q = 0; q < 8; q++) { y[q][0] = 0.f; y[q][1] = 0.f; }

    // online-softmax state for q = w (replicated in warp w's lanes)
    float m = -1e30f, l = 0.f;

    auto issue = [&](int c) {
        const float* sk; const float* sv; int n16;
        if (c < NCHUNK) {
            sk = pkb + (size_t)c * CH * HD;
            sv = pvb + (size_t)c * CH * HD;
            n16 = CH * 16;
        } else {
            sk = okb + (size_t)TP * HD;
            sv = ovb + (size_t)TP * HD;
            n16 = TN * 16;
        }
        float4* kb = ks4 + (c & 1) * 1024;
        float4* vb = vs4 + (c & 1) * 1024;
#pragma unroll
        for (int i = 0; i < 4; i++) {
            int fi = tid + i * 256;
            if (fi < n16) {
                int ky = fi >> 4, f = fi & 15;
                int sidx = ky * 16 + (f ^ (ky & 15));   // XOR swizzle, 16B granular
                cpa16(kb + sidx, sk + fi * 4);
                cpa16(vb + sidx, sv + fi * 4);
            }
        }
        asm volatile("cp.async.commit_group;\n");
    };

    issue(0);

    for (int c = 0; c <= NCHUNK; c++) {
        if (c < NCHUNK) {
            issue(c + 1);
            asm volatile("cp.async.wait_group 1;\n");
        } else {
            asm volatile("cp.async.wait_group 0;\n");
        }
        __syncthreads();

        // ---------------- scores (each K element read once from smem) ------
        const float4* kb = ks4 + (c & 1) * 1024;
        float4 kv[4];
#pragma unroll
        for (int i = 0; i < 4; i++)
            kv[i] = kb[key * 16 + ((dseg * 4 + i) ^ (key & 15))];

        if (c < NCHUNK) {   // copy-out K from the same registers
#pragma unroll
            for (int i = 0; i < 4; i++)
                *(float4*)&okb[((size_t)(c * CH) + key) * HD + dseg * 16 + i * 4] = kv[i];
        }

        float part[8];
#pragma unroll
        for (int q = 0; q < 8; q++) {
            float s = 0.f;
#pragma unroll
            for (int i = 0; i < 4; i++) {
                float4 qv = ((const float4*)qs)[q * 16 + dseg * 4 + i]; // warp-uniform
                s += kv[i].x * qv.x + kv[i].y * qv.y + kv[i].z * qv.z + kv[i].w * qv.w;
            }
            part[q] = s;
        }
#pragma unroll
        for (int q = 0; q < 8; q++)
            sp[dseg * 512 + q * 64 + key] = part[q];
        __syncthreads();

        // ---------------- softmax: warp w handles query q = w --------------
        {
            float s1 = sp[0 * 512 + w * 64 + lane] + sp[1 * 512 + w * 64 + lane]
                     + sp[2 * 512 + w * 64 + lane] + sp[3 * 512 + w * 64 + lane];
            float s2 = sp[0 * 512 + w * 64 + lane + 32] + sp[1 * 512 + w * 64 + lane + 32]
                     + sp[2 * 512 + w * 64 + lane + 32] + sp[3 * 512 + w * 64 + lane + 32];
            if (c == NCHUNK) {  // causal mask on the 8 new keys
                if (!(lane < TN && lane <= w)) s1 = -1e30f;
                s2 = -1e30f;
            }
            float cm = fmaxf(s1, s2);
#pragma unroll
            for (int o = 16; o > 0; o >>= 1)
                cm = fmaxf(cm, __shfl_xor_sync(0xffffffffu, cm, o));
            float mn = fmaxf(m, cm);
            float a  = __expf(m - mn);
            float p1 = __expf(s1 - mn);
            float p2 = __expf(s2 - mn);
            float ps = p1 + p2;
#pragma unroll
            for (int o = 16; o > 0; o >>= 1)
                ps += __shfl_xor_sync(0xffffffffu, ps, o);
            l = l * a + ps;
            m = mn;
            pb[w * 64 + lane]      = p1;
            pb[w * 64 + lane + 32] = p2;
            if (lane == 0) { al[w] = a; ls[w] = l; }
        }
        __syncthreads();

        // ---------------- PV (each V element read once from smem) ----------
        {
            const float* vbf = (const float*)(vs4 + (c & 1) * 1024);
            float2 vv[8];
#pragma unroll
            for (int jj = 0; jj < 8; jj++) {
                int j  = w * 8 + jj;
                int fo = (j * 16 + ((lane >> 1) ^ (j & 15))) * 4 + ((2 * lane) & 3);
                vv[jj] = *(const float2*)&vbf[fo];
            }
            if (c < NCHUNK) {   // copy-out V from the same registers
#pragma unroll
                for (int jj = 0; jj < 8; jj++) {
                    int j = w * 8 + jj;
                    *(float2*)&ovb[((size_t)(c * CH) + j) * HD + 2 * lane] = vv[jj];
                }
            }
#pragma unroll
            for (int q = 0; q < 8; q++) {
                float a  = al[q];
                float4 pa = ((const float4*)pb)[q * 16 + w * 2];     // warp-uniform
                float4 pc = ((const float4*)pb)[q * 16 + w * 2 + 1];
                float y0 = y[q][0] * a, y1 = y[q][1] * a;
                y0 += pa.x * vv[0].x + pa.y * vv[1].x + pa.z * vv[2].x + pa.w * vv[3].x
                    + pc.x * vv[4].x + pc.y * vv[5].x + pc.z * vv[6].x + pc.w * vv[7].x;
                y1 += pa.x * vv[0].y + pa.y * vv[1].y + pa.z * vv[2].y + pa.w * vv[3].y
                    + pc.x * vv[4].y + pc.y * vv[5].y + pc.z * vv[6].y + pc.w * vv[7].y;
                y[q][0] = y0; y[q][1] = y1;
            }
        }
        __syncthreads();
    }

    // ------------- epilogue: reduce partial y across the 8 key-group warps --
#pragma unroll
    for (int q = 0; q < 8; q++) {
        atomicAdd(&yt[q * 64 + 2 * lane],     y[q][0]);
        atomicAdd(&yt[q * 64 + 2 * lane + 1], y[q][1]);
    }
    __syncthreads();
    if (tid < 128) {
        int q = tid >> 4, d4 = tid & 15;
        float inv = 1.f / ls[q];
        float4 v = ((const float4*)yt)[q * 16 + d4];
        v.x *= inv; v.y *= inv; v.z *= inv; v.w *= inv;
        int b = bh >> 4, h = bh & 15;
        *(float4*)&g_y[(size_t)(b * TN + q) * CC + h * HD + d4 * 4] = v;
    }
}

// ---------------------------------------------------------------------------
extern "C" void kernel_launch(void* const* d_in, const int* in_sizes, int n_in,
                              void* d_out, int out_size)
{
    const float* x      = (const float*)d_in[0];
    const float* past_k = (const float*)d_in[1];
    const float* past_v = (const float*)d_in[2];
    const float* W_attn = (const float*)d_in[3];
    const float* b_attn = (const float*)d_in[4];
    const float* W_proj = (const float*)d_in[5];
    const float* b_proj = (const float*)d_in[6];

    float* out  = (float*)d_out;
    float* outk = out + OUT_K_OFF;
    float* outv = out + OUT_V_OFF;

    // host-side attribute set — not a stream op, safe under graph capture
    cudaFuncSetAttribute(attn_kernel, cudaFuncAttributeMaxDynamicSharedMemorySize,
                         SMEM_BYTES);

    // 1) QKV projection: q -> g_q (scaled), k_new/v_new -> out k/v tails
    gemm_kernel<0><<<192, 256>>>(x, W_attn, b_attn, nullptr, outk, outv);

    // 2) fused KV-cache copy + attention: y -> g_y, past k/v -> out k/v
    attn_kernel<<<NB * NH, 256, SMEM_BYTES>>>(past_k, past_v, outk, outv);

    // 3) output projection: g_y @ W_proj^T + b -> out[0:131072]
    gemm_kernel<1><<<64, 256>>>(nullptr, W_proj, b_proj, out, nullptr, nullptr);
}

// round 10
// speedup vs baseline: 1.4762x; 1.4762x over previous
#include <cuda_runtime.h>
#include <cstdint>

#define NB 16
#define TN 8
#define CC 1024
#define NH 16
#define HD 64
#define TP 4096
#define TF 4104
#define CH 64
#define NCHUNK 64
#define KSPLIT 8
#define KPER (CC / KSPLIT)            // 128
#define M0 8.0f
#define UNITS_PER_BH 8
#define NUNITS (256 * UNITS_PER_BH)   // 2048
#define UPSTRIDE 528

#define OUT_K_OFF  131072
#define KV_ELEMS   67239936           // 256*4104*64
#define OUT_V_OFF  (OUT_K_OFF + KV_ELEMS)

// attention dynamic smem (floats): ks 8192 | vs 8192 | qs 512 | sp 2048 | pb 512 | yt 512 | su 4
#define ATTN_SMEM ((8192 + 8192 + 512 + 2048 + 512 + 512 + 4) * 4)

// scratch (allocation-free rule: __device__ globals)
__device__ __align__(16) float g_q[256 * TN * HD];          // scaled q, [b][h][t][d]
__device__ __align__(16) float g_y[128 * CC];               // attention out (B,T,C)
__device__ __align__(16) float g_part[KSPLIT * 128 * 3072]; // split-k partials
__device__ __align__(16) float g_upart[NUNITS * UPSTRIDE];  // per-unit (y, l)
__device__ int g_ctr;                                        // persistent work counter

// ---------------------------------------------------------------------------
// Split-K GEMM partial: C_part[z] = X[64-row tile] @ W[64-col tile]^T over
// k in [z*128, z*128+128). 256 threads, 4x4 register tile per thread.
// MODE 0: X = x input, NCOLS=3072 (QKV).  MODE 1: X = g_y, NCOLS=1024 (proj).
// ---------------------------------------------------------------------------
template <int MODE>
__global__ __launch_bounds__(256) void gemm_partial(
    const float* __restrict__ Xp, const float* __restrict__ W)
{
    const int NCOLS = MODE ? 1024 : 3072;
    const float* X = MODE ? (const float*)g_y : Xp;

    __shared__ float xs[32][68];   // [k][row], transposed for vector LDS
    __shared__ float ws[32][68];   // [k][col]

    const int tid = threadIdx.x;
    const int tx  = tid & 15, ty = tid >> 4;
    const int n0  = blockIdx.x * 64;
    const int r0  = blockIdx.y * 64;
    const int k0  = blockIdx.z * KPER;

    float acc[4][4];
#pragma unroll
    for (int i = 0; i < 4; i++)
#pragma unroll
        for (int j = 0; j < 4; j++) acc[i][j] = 0.f;

    const int lrow = tid >> 3, lkq = tid & 7;

    for (int kt = 0; kt < KPER; kt += 32) {
        const int kb = k0 + kt;
#pragma unroll
        for (int h = 0; h < 2; h++) {
            int r = lrow + h * 32;
            float4 xv = *(const float4*)&X[(size_t)(r0 + r) * CC + kb + lkq * 4];
            xs[lkq * 4 + 0][r] = xv.x; xs[lkq * 4 + 1][r] = xv.y;
            xs[lkq * 4 + 2][r] = xv.z; xs[lkq * 4 + 3][r] = xv.w;
            float4 wv = *(const float4*)&W[(size_t)(n0 + r) * CC + kb + lkq * 4];
            ws[lkq * 4 + 0][r] = wv.x; ws[lkq * 4 + 1][r] = wv.y;
            ws[lkq * 4 + 2][r] = wv.z; ws[lkq * 4 + 3][r] = wv.w;
        }
        __syncthreads();
#pragma unroll
        for (int k = 0; k < 32; k++) {
            float4 a = *(const float4*)&xs[k][ty * 4];
            float4 b = *(const float4*)&ws[k][tx * 4];
            float av[4] = {a.x, a.y, a.z, a.w};
            float bv[4] = {b.x, b.y, b.z, b.w};
#pragma unroll
            for (int i = 0; i < 4; i++)
#pragma unroll
                for (int j = 0; j < 4; j++) acc[i][j] += av[i] * bv[j];
        }
        __syncthreads();
    }

    float* dst = g_part + (size_t)blockIdx.z * 128 * NCOLS;
#pragma unroll
    for (int i = 0; i < 4; i++)
        *(float4*)&dst[(size_t)(r0 + ty * 4 + i) * NCOLS + n0 + tx * 4] =
            make_float4(acc[i][0], acc[i][1], acc[i][2], acc[i][3]);
}

// ---------------------------------------------------------------------------
// Split-K reduce + bias + scatter.
// MODE 0: -> g_q (scaled 0.125), out_k/out_v tails; also resets g_ctr.
// MODE 1: -> out[row*1024 + n].
// ---------------------------------------------------------------------------
template <int MODE>
__global__ __launch_bounds__(256) void gemm_reduce(
    const float* __restrict__ bias, float* __restrict__ out,
    float* __restrict__ outk, float* __restrict__ outv)
{
    const int NCOLS = MODE ? 1024 : 3072;
    const int gid = blockIdx.x * 256 + threadIdx.x;
    const int row = gid / (NCOLS / 4);
    const int n   = (gid % (NCOLS / 4)) * 4;

    float4 s = make_float4(0.f, 0.f, 0.f, 0.f);
#pragma unroll
    for (int p = 0; p < KSPLIT; p++) {
        float4 v = *(const float4*)&g_part[(size_t)p * 128 * NCOLS + (size_t)row * NCOLS + n];
        s.x += v.x; s.y += v.y; s.z += v.z; s.w += v.w;
    }
    float4 bv = *(const float4*)&bias[n];
    s.x += bv.x; s.y += bv.y; s.z += bv.z; s.w += bv.w;

    if (MODE == 0) {
        int b = row >> 3, t = row & 7, d = n & 63;
        if (n < 1024) {
            int h = n >> 6;
            float4 q = make_float4(s.x * 0.125f, s.y * 0.125f, s.z * 0.125f, s.w * 0.125f);
            *(float4*)&g_q[((b * NH + h) * TN + t) * HD + d] = q;
        } else if (n < 2048) {
            int h = (n - 1024) >> 6;
            *(float4*)&outk[((size_t)(b * NH + h) * TF + TP + t) * HD + d] = s;
        } else {
            int h = (n - 2048) >> 6;
            *(float4*)&outv[((size_t)(b * NH + h) * TF + TP + t) * HD + d] = s;
        }
        if (gid == 0) g_ctr = 0;    // reset persistent work counter before attn
    } else {
        *(float4*)&out[(size_t)row * 1024 + n] = s;
    }
}

// ---------------------------------------------------------------------------
__device__ __forceinline__ void cpa16(void* dst, const void* src) {
    uint32_t d = (uint32_t)__cvta_generic_to_shared(dst);
    asm volatile("cp.async.cg.shared.global [%0], [%1], 16;\n" ::"r"(d), "l"(src));
}

// ---------------------------------------------------------------------------
// Persistent fused KV-cache copy + attention. grid = 2*SMs, 256 threads.
// Work units: 2048 = 256 (b,h) x 8 key-range parts of 8 chunks each; part 7
// also handles the 8-key causal tail. Fixed-max softmax (M0) makes partial
// results associative: each unit writes (sum p*v, sum p) to a FIXED slot in
// g_upart (deterministic regardless of which block processed it); a combine
// kernel reduces the 8 parts per (b,h) in fixed order.
// ---------------------------------------------------------------------------
__global__ __launch_bounds__(256, 2) void attn_kernel(
    const float* __restrict__ pk, const float* __restrict__ pv,
    float* __restrict__ outk, float* __restrict__ outv)
{
    extern __shared__ float sm[];
    float4* ks4 = (float4*)sm;              // 2 bufs * 1024 f4
    float4* vs4 = ks4 + 2048;               // 2 bufs * 1024 f4
    float*  qs  = (float*)(vs4 + 2048);     // 512
    float*  sp  = qs + 512;                 // 2048 score partials
    float*  pb  = sp + 2048;                // 512 probabilities
    float*  yt  = pb + 512;                 // 512 y reduction
    int*    su  = (int*)(yt + 512);

    const int tid  = threadIdx.x;
    const int w    = tid >> 5, lane = tid & 31;
    const int key  = (w & 1) * 32 + lane;   // score mapping
    const int dseg = w >> 1;

    for (;;) {
        if (tid == 0) *su = atomicAdd(&g_ctr, 1);
        __syncthreads();
        const int u = *su;
        if (u >= NUNITS) break;

        const int bh = u >> 3, part = u & 7;
        const float* pkb = pk + (size_t)bh * TP * HD;
        const float* pvb = pv + (size_t)bh * TP * HD;
        float* okb = outk + (size_t)bh * TF * HD;
        float* ovb = outv + (size_t)bh * TF * HD;
        const int c0  = part * 8;
        const int nch = (part == 7) ? 9 : 8;

        auto issue = [&](int c) {
            const float* sk; const float* sv; int n16;
            if (c < NCHUNK) {
                sk = pkb + (size_t)c * CH * HD;
                sv = pvb + (size_t)c * CH * HD;
                n16 = CH * 16;
            } else {                               // 8 new keys from out tails
                sk = okb + (size_t)TP * HD;
                sv = ovb + (size_t)TP * HD;
                n16 = TN * 16;
            }
            float4* kb = ks4 + (c & 1) * 1024;
            float4* vb = vs4 + (c & 1) * 1024;
#pragma unroll
            for (int i = 0; i < 4; i++) {
                int fi = tid + i * 256;
                if (fi < n16) {
                    int ky = fi >> 4, f = fi & 15;
                    int sidx = ky * 16 + (f ^ (ky & 15));   // XOR swizzle (16B)
                    cpa16(kb + sidx, sk + fi * 4);
                    cpa16(vb + sidx, sv + fi * 4);
                }
            }
            asm volatile("cp.async.commit_group;\n");
        };

        issue(c0);
        if (tid < 128) {
            ((float4*)qs)[tid] = ((const float4*)g_q)[bh * 128 + tid];
            ((float4*)yt)[tid] = make_float4(0.f, 0.f, 0.f, 0.f);
        }
        float l = 0.f;
        float y[8][2];
#pragma unroll
        for (int q = 0; q < 8; q++) { y[q][0] = 0.f; y[q][1] = 0.f; }

        for (int ci = 0; ci < nch; ci++) {
            const int c = c0 + ci;
            if (ci + 1 < nch) {
                issue(c + 1);
                asm volatile("cp.async.wait_group 1;\n");
            } else {
                asm volatile("cp.async.wait_group 0;\n");
            }
            __syncthreads();

            const float4* kb = ks4 + (c & 1) * 1024;
            const float4* vb = vs4 + (c & 1) * 1024;

            // coalesced copy-out (the "write KV cache" half of the fusion)
            if (c < NCHUNK) {
#pragma unroll
                for (int i = 0; i < 4; i++) {
                    int fi = tid + i * 256;
                    int ky = fi >> 4, f = fi & 15;
                    int sidx = ky * 16 + (f ^ (ky & 15));
                    *(float4*)&okb[(size_t)c * 4096 + fi * 4] = kb[sidx];
                    *(float4*)&ovb[(size_t)c * 4096 + fi * 4] = vb[sidx];
                }
            }

            // ---- scores: thread = (key, 16-d segment) ----
            float4 kv[4];
#pragma unroll
            for (int i = 0; i < 4; i++)
                kv[i] = kb[key * 16 + ((dseg * 4 + i) ^ (key & 15))];
            float ps[8];
#pragma unroll
            for (int q = 0; q < 8; q++) {
                float s = 0.f;
#pragma unroll
                for (int i = 0; i < 4; i++) {
                    float4 qv = ((const float4*)qs)[q * 16 + dseg * 4 + i]; // uniform
                    s += kv[i].x * qv.x + kv[i].y * qv.y + kv[i].z * qv.z + kv[i].w * qv.w;
                }
                ps[q] = s;
            }
#pragma unroll
            for (int q = 0; q < 8; q++)
                sp[dseg * 512 + q * 64 + key] = ps[q];
            __syncthreads();

            // ---- fixed-max softmax: warp w -> query w, keys lane/lane+32 ----
            {
                float s1 = sp[w * 64 + lane]        + sp[512 + w * 64 + lane]
                         + sp[1024 + w * 64 + lane] + sp[1536 + w * 64 + lane];
                float s2 = sp[w * 64 + lane + 32]        + sp[512 + w * 64 + lane + 32]
                         + sp[1024 + w * 64 + lane + 32] + sp[1536 + w * 64 + lane + 32];
                if (c == NCHUNK) {      // causal mask on the 8 new keys
                    if (!(lane < TN && lane <= w)) s1 = -1e30f;
                    s2 = -1e30f;
                }
                float p1 = __expf(s1 - M0);
                float p2 = __expf(s2 - M0);
                l += p1 + p2;
                pb[w * 64 + lane]      = p1;
                pb[w * 64 + lane + 32] = p2;
            }
            __syncthreads();

            // ---- PV: warp w -> keys w*8..w*8+7, lane -> d = 2*lane,2*lane+1 ----
            {
                const float* vbf = (const float*)vb;
                float2 vv[8];
#pragma unroll
                for (int jj = 0; jj < 8; jj++) {
                    int j  = w * 8 + jj;
                    int fo = (j * 16 + ((lane >> 1) ^ (j & 15))) * 4 + ((2 * lane) & 3);
                    vv[jj] = *(const float2*)&vbf[fo];
                }
#pragma unroll
                for (int q = 0; q < 8; q++) {
                    float4 pa = ((const float4*)pb)[q * 16 + w * 2];     // uniform
                    float4 pc = ((const float4*)pb)[q * 16 + w * 2 + 1];
                    y[q][0] += pa.x * vv[0].x + pa.y * vv[1].x + pa.z * vv[2].x + pa.w * vv[3].x
                             + pc.x * vv[4].x + pc.y * vv[5].x + pc.z * vv[6].x + pc.w * vv[7].x;
                    y[q][1] += pa.x * vv[0].y + pa.y * vv[1].y + pa.z * vv[2].y + pa.w * vv[3].y
                             + pc.x * vv[4].y + pc.y * vv[5].y + pc.z * vv[6].y + pc.w * vv[7].y;
                }
            }
            __syncthreads();
        }

        // ---- unit epilogue: reduce y across key-group warps, write slot ----
#pragma unroll
        for (int q = 0; q < 8; q++) {
            atomicAdd(&yt[q * 64 + 2 * lane],     y[q][0]);
            atomicAdd(&yt[q * 64 + 2 * lane + 1], y[q][1]);
        }
#pragma unroll
        for (int o = 16; o > 0; o >>= 1) l += __shfl_xor_sync(0xffffffffu, l, o);
        __syncthreads();
        float* up = g_upart + (size_t)u * UPSTRIDE;
        if (tid < 128) ((float4*)up)[tid] = ((const float4*)yt)[tid];
        if (lane == 0) up[512 + w] = l;
    }
}

// ---------------------------------------------------------------------------
// Combine the 8 fixed parts per (b,h): y = sum y_p / sum l_p -> g_y.
// Fixed iteration order => deterministic.
// ---------------------------------------------------------------------------
__global__ __launch_bounds__(128) void combine_kernel()
{
    const int bh  = blockIdx.x;
    const int tid = threadIdx.x;       // q = tid>>4, d4 = tid&15
    const int q   = tid >> 4, d4 = tid & 15;

    float4 ys = make_float4(0.f, 0.f, 0.f, 0.f);
    float  ls = 0.f;
#pragma unroll
    for (int p = 0; p < UNITS_PER_BH; p++) {
        const float* up = g_upart + (size_t)(bh * UNITS_PER_BH + p) * UPSTRIDE;
        float4 v = ((const float4*)up)[tid];
        ys.x += v.x; ys.y += v.y; ys.z += v.z; ys.w += v.w;
        ls += up[512 + q];
    }
    float inv = 1.f / ls;
    ys.x *= inv; ys.y *= inv; ys.z *= inv; ys.w *= inv;
    int b = bh >> 4, h = bh & 15;
    *(float4*)&g_y[(size_t)(b * TN + q) * CC + h * HD + d4 * 4] = ys;
}

// ---------------------------------------------------------------------------
extern "C" void kernel_launch(void* const* d_in, const int* in_sizes, int n_in,
                              void* d_out, int out_size)
{
    const float* x      = (const float*)d_in[0];
    const float* past_k = (const float*)d_in[1];
    const float* past_v = (const float*)d_in[2];
    const float* W_attn = (const float*)d_in[3];
    const float* b_attn = (const float*)d_in[4];
    const float* W_proj = (const float*)d_in[5];
    const float* b_proj = (const float*)d_in[6];

    float* out  = (float*)d_out;
    float* outk = out + OUT_K_OFF;
    float* outv = out + OUT_V_OFF;

    int dev = 0, nsm = 148;
    cudaGetDevice(&dev);
    cudaDeviceGetAttribute(&nsm, cudaDevAttrMultiProcessorCount, dev);

    // host-side attribute set — not a stream op, capture-safe
    cudaFuncSetAttribute(attn_kernel, cudaFuncAttributeMaxDynamicSharedMemorySize,
                         ATTN_SMEM);

    // 1) QKV projection (split-K): partials -> reduce -> g_q + out k/v tails
    gemm_partial<0><<<dim3(48, 2, KSPLIT), 256>>>(x, W_attn);
    gemm_reduce<0><<<384, 256>>>(b_attn, nullptr, outk, outv);

    // 2) persistent fused KV-copy + attention, then deterministic combine
    attn_kernel<<<2 * nsm, 256, ATTN_SMEM>>>(past_k, past_v, outk, outv);
    combine_kernel<<<256, 128>>>();

    // 3) output projection (split-K)
    gemm_partial<1><<<dim3(16, 2, KSPLIT), 256>>>(nullptr, W_proj);
    gemm_reduce<1><<<128, 256>>>(b_proj, out, nullptr, nullptr);
}

// round 11
// speedup vs baseline: 1.5006x; 1.0166x over previous
#include <cuda_runtime.h>
#include <cstdint>

#define NB 16
#define TN 8
#define CC 1024
#define NH 16
#define HD 64
#define TP 4096
#define TF 4104
#define CH 64
#define NCHUNK 64
#define KSPLIT 8
#define KPER (CC / KSPLIT)            // 128
#define M0 8.0f
#define UNITS_PER_BH 8
#define NUNITS (256 * UNITS_PER_BH)   // 2048
#define UPSTRIDE 528

#define OUT_K_OFF  131072
#define KV_ELEMS   67239936           // 256*4104*64
#define OUT_V_OFF  (OUT_K_OFF + KV_ELEMS)

// attn dynamic smem (floats): ks 8192 | vs 8192 | qs 512 | sp 2048 | pb 1024(dup) | yt 512 | su 4
#define ATTN_SMEM ((8192 + 8192 + 512 + 2048 + 1024 + 512 + 4) * 4)

typedef unsigned long long u64;

// scratch (allocation-free rule: __device__ globals)
__device__ __align__(16) float g_q[256 * TN * HD];          // scaled q, [b][h][t][d]
__device__ __align__(16) float g_y[128 * CC];               // attention out (B,T,C)
__device__ __align__(16) float g_part[KSPLIT * 128 * 3072]; // split-k partials
__device__ __align__(16) float g_upart[NUNITS * UPSTRIDE];  // per-unit (y, l)
__device__ int g_ctr;                                        // persistent work counter

// ---------------------------------------------------------------------------
// packed fp32x2 helpers (sm_103a FFMA2 — exact fp32, 2x fma-pipe throughput)
// ---------------------------------------------------------------------------
__device__ __forceinline__ u64 ffma2(u64 a, u64 b, u64 c) {
    u64 d;
    asm("fma.rn.f32x2 %0, %1, %2, %3;" : "=l"(d) : "l"(a), "l"(b), "l"(c));
    return d;
}
__device__ __forceinline__ u64 dup2(float x) {
    u64 r; asm("mov.b64 %0, {%1, %2};" : "=l"(r) : "f"(x), "f"(x)); return r;
}
__device__ __forceinline__ float2 up2(u64 v) {
    float2 f; asm("mov.b64 {%0, %1}, %2;" : "=f"(f.x), "=f"(f.y) : "l"(v)); return f;
}

// ---------------------------------------------------------------------------
// Split-K GEMM partial (FFMA2 inner loop). 256 threads, 4x4 register tile.
// MODE 0: X = x input, NCOLS=3072 (QKV).  MODE 1: X = g_y, NCOLS=1024 (proj).
// ---------------------------------------------------------------------------
template <int MODE>
__global__ __launch_bounds__(256) void gemm_partial(
    const float* __restrict__ Xp, const float* __restrict__ W)
{
    const int NCOLS = MODE ? 1024 : 3072;
    const float* X = MODE ? (const float*)g_y : Xp;

    __shared__ float xs[32][68];   // [k][row]  (68-stride: 16B-aligned rows, no conflicts)
    __shared__ float ws[32][68];   // [k][col]

    const int tid = threadIdx.x;
    const int tx  = tid & 15, ty = tid >> 4;
    const int n0  = blockIdx.x * 64;
    const int r0  = blockIdx.y * 64;
    const int k0  = blockIdx.z * KPER;

    u64 a01[4], a23[4];
#pragma unroll
    for (int i = 0; i < 4; i++) { a01[i] = 0ull; a23[i] = 0ull; }

    const int lrow = tid >> 3, lkq = tid & 7;

    for (int kt = 0; kt < KPER; kt += 32) {
        const int kb = k0 + kt;
#pragma unroll
        for (int h = 0; h < 2; h++) {
            int r = lrow + h * 32;
            float4 xv = *(const float4*)&X[(size_t)(r0 + r) * CC + kb + lkq * 4];
            xs[lkq * 4 + 0][r] = xv.x; xs[lkq * 4 + 1][r] = xv.y;
            xs[lkq * 4 + 2][r] = xv.z; xs[lkq * 4 + 3][r] = xv.w;
            float4 wv = *(const float4*)&W[(size_t)(n0 + r) * CC + kb + lkq * 4];
            ws[lkq * 4 + 0][r] = wv.x; ws[lkq * 4 + 1][r] = wv.y;
            ws[lkq * 4 + 2][r] = wv.z; ws[lkq * 4 + 3][r] = wv.w;
        }
        __syncthreads();
#pragma unroll
        for (int k = 0; k < 32; k++) {
            float4 a = *(const float4*)&xs[k][ty * 4];          // broadcast
            ulonglong2 b2 = *(const ulonglong2*)&ws[k][tx * 4]; // (b0,b1),(b2,b3)
            float av[4] = {a.x, a.y, a.z, a.w};
#pragma unroll
            for (int i = 0; i < 4; i++) {
                u64 ad = dup2(av[i]);                           // alu pipe, overlaps fma
                a01[i] = ffma2(ad, b2.x, a01[i]);
                a23[i] = ffma2(ad, b2.y, a23[i]);
            }
        }
        __syncthreads();
    }

    float* dst = g_part + (size_t)blockIdx.z * 128 * NCOLS;
#pragma unroll
    for (int i = 0; i < 4; i++) {
        float2 l01 = up2(a01[i]), l23 = up2(a23[i]);
        *(float4*)&dst[(size_t)(r0 + ty * 4 + i) * NCOLS + n0 + tx * 4] =
            make_float4(l01.x, l01.y, l23.x, l23.y);
    }
}

// ---------------------------------------------------------------------------
// Split-K reduce + bias + scatter.
// MODE 0: -> g_q (scaled 0.125), out_k/out_v tails; also resets g_ctr.
// MODE 1: -> out[row*1024 + n].
// ---------------------------------------------------------------------------
template <int MODE>
__global__ __launch_bounds__(256) void gemm_reduce(
    const float* __restrict__ bias, float* __restrict__ out,
    float* __restrict__ outk, float* __restrict__ outv)
{
    const int NCOLS = MODE ? 1024 : 3072;
    const int gid = blockIdx.x * 256 + threadIdx.x;
    const int row = gid / (NCOLS / 4);
    const int n   = (gid % (NCOLS / 4)) * 4;

    float4 s = make_float4(0.f, 0.f, 0.f, 0.f);
#pragma unroll
    for (int p = 0; p < KSPLIT; p++) {
        float4 v = *(const float4*)&g_part[(size_t)p * 128 * NCOLS + (size_t)row * NCOLS + n];
        s.x += v.x; s.y += v.y; s.z += v.z; s.w += v.w;
    }
    float4 bv = *(const float4*)&bias[n];
    s.x += bv.x; s.y += bv.y; s.z += bv.z; s.w += bv.w;

    if (MODE == 0) {
        int b = row >> 3, t = row & 7, d = n & 63;
        if (n < 1024) {
            int h = n >> 6;
            float4 q = make_float4(s.x * 0.125f, s.y * 0.125f, s.z * 0.125f, s.w * 0.125f);
            *(float4*)&g_q[((b * NH + h) * TN + t) * HD + d] = q;
        } else if (n < 2048) {
            int h = (n - 1024) >> 6;
            *(float4*)&outk[((size_t)(b * NH + h) * TF + TP + t) * HD + d] = s;
        } else {
            int h = (n - 2048) >> 6;
            *(float4*)&outv[((size_t)(b * NH + h) * TF + TP + t) * HD + d] = s;
        }
        if (gid == 0) g_ctr = 0;    // reset persistent work counter before attn
    } else {
        *(float4*)&out[(size_t)row * 1024 + n] = s;
    }
}

// ---------------------------------------------------------------------------
__device__ __forceinline__ void cpa16(void* dst, const void* src) {
    uint32_t d = (uint32_t)__cvta_generic_to_shared(dst);
    asm volatile("cp.async.cg.shared.global [%0], [%1], 16;\n" ::"r"(d), "l"(src));
}

// ---------------------------------------------------------------------------
// Persistent fused KV-cache copy + attention, cross-unit pipelined.
// 2048 units = 256 (b,h) x 8 key-range parts; part 7 adds the 8-key causal
// tail. The cp.async double-buffer pipeline never drains: the next unit's
// chunk 0 is issued in place of the current unit's chunk N. Buffer parity is
// tracked by monotonic issue/consume counters (unit lengths 8 or 9 chunks).
// Fixed-max softmax (M0) keeps partials associative -> deterministic combine.
// ---------------------------------------------------------------------------
__global__ __launch_bounds__(256, 2) void attn_kernel(
    const float* __restrict__ pk, const float* __restrict__ pv,
    float* __restrict__ outk, float* __restrict__ outv)
{
    extern __shared__ float sm[];
    float4* ks4 = (float4*)sm;              // 2 bufs * 1024 f4
    float4* vs4 = ks4 + 2048;               // 2 bufs * 1024 f4
    float*  qs  = (float*)(vs4 + 2048);     // 512
    float*  sp  = qs + 512;                 // 2048 score partials
    float*  pb  = sp + 2048;                // 1024 duplicated probabilities (p,p)
    float*  yt  = pb + 1024;                // 512 y reduction
    int*    su  = (int*)(yt + 512);         // [0]=current unit, [1]=next unit

    const int tid  = threadIdx.x;
    const int w    = tid >> 5, lane = tid & 31;
    const int key  = (w & 1) * 32 + lane;   // score mapping
    const int dseg = w >> 1;

    if (tid == 0) su[0] = atomicAdd(&g_ctr, 1);
    __syncthreads();
    int u = su[0];
    if (u >= NUNITS) return;

    int icnt = 0, ccnt = 0;     // issued / consumed chunk counters (buffer parity)

    int bh = u >> 3, part = u & 7;
    const float* pkb = pk + (size_t)bh * TP * HD;
    const float* pvb = pv + (size_t)bh * TP * HD;
    float* okb = outk + (size_t)bh * TF * HD;
    float* ovb = outv + (size_t)bh * TF * HD;

    auto issue_raw = [&](const float* ksrc, const float* vsrc, int n16, int buf) {
        float4* kb = ks4 + buf * 1024;
        float4* vb = vs4 + buf * 1024;
#pragma unroll
        for (int i = 0; i < 4; i++) {
            int fi = tid + i * 256;
            if (fi < n16) {
                int ky = fi >> 4, f = fi & 15;
                int sidx = ky * 16 + (f ^ (ky & 15));   // XOR swizzle (16B)
                cpa16(kb + sidx, ksrc + fi * 4);
                cpa16(vb + sidx, vsrc + fi * 4);
            }
        }
        asm volatile("cp.async.commit_group;\n");
    };
    auto issue_c = [&](const float* pk_, const float* pv_, float* ok_, float* ov_,
                       int c, int buf) {
        if (c < NCHUNK)
            issue_raw(pk_ + (size_t)c * CH * HD, pv_ + (size_t)c * CH * HD, CH * 16, buf);
        else
            issue_raw(ok_ + (size_t)TP * HD, ov_ + (size_t)TP * HD, TN * 16, buf);
    };

    issue_c(pkb, pvb, okb, ovb, part * 8, (icnt++) & 1);

    if (tid < 128) {
        ((float4*)qs)[tid] = ((const float4*)g_q)[bh * 128 + tid];
        ((float4*)yt)[tid] = make_float4(0.f, 0.f, 0.f, 0.f);
    }

    for (;;) {
        const int c0  = part * 8;
        const int nch = (part == 7) ? 9 : 8;
        if (tid == 0) su[1] = atomicAdd(&g_ctr, 1);   // prefetch next unit id

        float l = 0.f;
        u64 y2[8];
#pragma unroll
        for (int q = 0; q < 8; q++) y2[q] = 0ull;

        int un = NUNITS;

        for (int ci = 0; ci < nch; ci++) {
            const int c = c0 + ci;
            if (ci + 1 < nch) {
                issue_c(pkb, pvb, okb, ovb, c + 1, (icnt++) & 1);
                asm volatile("cp.async.wait_group 1;\n");
            } else {
                un = su[1];   // ordered by the barriers of earlier iterations
                if (un < NUNITS) {
                    int nbh = un >> 3, npart = un & 7;
                    issue_c(pk + (size_t)nbh * TP * HD, pv + (size_t)nbh * TP * HD,
                            outk + (size_t)nbh * TF * HD, outv + (size_t)nbh * TF * HD,
                            npart * 8, (icnt++) & 1);
                    asm volatile("cp.async.wait_group 1;\n");
                } else {
                    asm volatile("cp.async.wait_group 0;\n");
                }
            }
            __syncthreads();   // A: chunk data visible to all threads

            const int buf = (ccnt++) & 1;
            const float4*     kb  = ks4 + buf * 1024;
            const float4*     vb  = vs4 + buf * 1024;
            const ulonglong2* kb2 = (const ulonglong2*)kb;
            const float*      vbf = (const float*)vb;

            // coalesced copy-out (the "write KV cache" half of the fusion)
            if (c < NCHUNK) {
#pragma unroll
                for (int i = 0; i < 4; i++) {
                    int fi = tid + i * 256;
                    int ky = fi >> 4, f = fi & 15;
                    int sidx = ky * 16 + (f ^ (ky & 15));
                    *(float4*)&okb[(size_t)c * 4096 + fi * 4] = kb[sidx];
                    *(float4*)&ovb[(size_t)c * 4096 + fi * 4] = vb[sidx];
                }
            }

            // ---- scores (FFMA2, operands pair-packed for free) ----
            ulonglong2 kv2[4];
#pragma unroll
            for (int i = 0; i < 4; i++)
                kv2[i] = kb2[key * 16 + ((dseg * 4 + i) ^ (key & 15))];
            float ps[8];
#pragma unroll
            for (int q = 0; q < 8; q++) {
                u64 s2 = 0ull;
#pragma unroll
                for (int i = 0; i < 4; i++) {
                    ulonglong2 qv2 = ((const ulonglong2*)qs)[q * 16 + dseg * 4 + i];
                    s2 = ffma2(kv2[i].x, qv2.x, s2);
                    s2 = ffma2(kv2[i].y, qv2.y, s2);
                }
                float2 ss = up2(s2);
                ps[q] = ss.x + ss.y;
            }
#pragma unroll
            for (int q = 0; q < 8; q++)
                sp[dseg * 512 + q * 64 + key] = ps[q];
            __syncthreads();   // B

            // ---- fixed-max softmax: warp w -> query w; write (p,p) pairs ----
            {
                float s1 = sp[w * 64 + lane]        + sp[512 + w * 64 + lane]
                         + sp[1024 + w * 64 + lane] + sp[1536 + w * 64 + lane];
                float s2v = sp[w * 64 + lane + 32]        + sp[512 + w * 64 + lane + 32]
                          + sp[1024 + w * 64 + lane + 32] + sp[1536 + w * 64 + lane + 32];
                if (c == NCHUNK) {      // causal mask on the 8 new keys
                    if (!(lane < TN && lane <= w)) s1 = -1e30f;
                    s2v = -1e30f;
                }
                float p1 = __expf(s1 - M0);
                float p2 = __expf(s2v - M0);
                l += p1 + p2;
                *(u64*)&pb[(w * 64 + lane) * 2]      = dup2(p1);
                *(u64*)&pb[(w * 64 + lane + 32) * 2] = dup2(p2);
            }
            __syncthreads();   // C

            // ---- PV (FFMA2): warp w -> keys w*8..w*8+7, lane -> d pair ----
            {
                u64 vvp[8];
#pragma unroll
                for (int jj = 0; jj < 8; jj++) {
                    int j  = w * 8 + jj;
                    int fo = (j * 16 + ((lane >> 1) ^ (j & 15))) * 4 + ((2 * lane) & 3);
                    vvp[jj] = *(const u64*)&vbf[fo];
                }
#pragma unroll
                for (int q = 0; q < 8; q++) {
                    ulonglong2 p0 = ((const ulonglong2*)pb)[q * 32 + w * 4 + 0]; // uniform
                    ulonglong2 p1 = ((const ulonglong2*)pb)[q * 32 + w * 4 + 1];
                    ulonglong2 p2 = ((const ulonglong2*)pb)[q * 32 + w * 4 + 2];
                    ulonglong2 p3 = ((const ulonglong2*)pb)[q * 32 + w * 4 + 3];
                    u64 acc = y2[q];
                    acc = ffma2(p0.x, vvp[0], acc); acc = ffma2(p0.y, vvp[1], acc);
                    acc = ffma2(p1.x, vvp[2], acc); acc = ffma2(p1.y, vvp[3], acc);
                    acc = ffma2(p2.x, vvp[4], acc); acc = ffma2(p2.y, vvp[5], acc);
                    acc = ffma2(p3.x, vvp[6], acc); acc = ffma2(p3.y, vvp[7], acc);
                    y2[q] = acc;
                }
            }
            __syncthreads();   // D: protects K/V buffer + sp/pb reuse
        }

        // ---- unit epilogue: reduce y across key-group warps, write slot ----
#pragma unroll
        for (int q = 0; q < 8; q++) {
            float2 yq = up2(y2[q]);
            atomicAdd(&yt[q * 64 + 2 * lane],     yq.x);
            atomicAdd(&yt[q * 64 + 2 * lane + 1], yq.y);
        }
#pragma unroll
        for (int o = 16; o > 0; o >>= 1) l += __shfl_xor_sync(0xffffffffu, l, o);
        __syncthreads();
        float* up = g_upart + (size_t)u * UPSTRIDE;
        if (tid < 128) ((float4*)up)[tid] = ((const float4*)yt)[tid];
        if (lane == 0) up[512 + w] = l;

        u = un;
        if (u >= NUNITS) break;
        bh = u >> 3; part = u & 7;
        pkb = pk + (size_t)bh * TP * HD;
        pvb = pv + (size_t)bh * TP * HD;
        okb = outk + (size_t)bh * TF * HD;
        ovb = outv + (size_t)bh * TF * HD;
        __syncthreads();       // upart reads of yt complete before re-zero
        if (tid < 128) {
            ((float4*)qs)[tid] = ((const float4*)g_q)[bh * 128 + tid];
            ((float4*)yt)[tid] = make_float4(0.f, 0.f, 0.f, 0.f);
        }
        // next unit's chunk 0 is already in flight (issued at last chunk above)
    }
}

// ---------------------------------------------------------------------------
// Combine the 8 fixed parts per (b,h): y = sum y_p / sum l_p -> g_y.
// Fixed iteration order => deterministic.
// ---------------------------------------------------------------------------
__global__ __launch_bounds__(128) void combine_kernel()
{
    const int bh  = blockIdx.x;
    const int tid = threadIdx.x;
    const int q   = tid >> 4, d4 = tid & 15;

    float4 ys = make_float4(0.f, 0.f, 0.f, 0.f);
    float  ls = 0.f;
#pragma unroll
    for (int p = 0; p < UNITS_PER_BH; p++) {
        const float* up = g_upart + (size_t)(bh * UNITS_PER_BH + p) * UPSTRIDE;
        float4 v = ((const float4*)up)[tid];
        ys.x += v.x; ys.y += v.y; ys.z += v.z; ys.w += v.w;
        ls += up[512 + q];
    }
    float inv = 1.f / ls;
    ys.x *= inv; ys.y *= inv; ys.z *= inv; ys.w *= inv;
    int b = bh >> 4, h = bh & 15;
    *(float4*)&g_y[(size_t)(b * TN + q) * CC + h * HD + d4 * 4] = ys;
}

// ---------------------------------------------------------------------------
extern "C" void kernel_launch(void* const* d_in, const int* in_sizes, int n_in,
                              void* d_out, int out_size)
{
    const float* x      = (const float*)d_in[0];
    const float* past_k = (const float*)d_in[1];
    const float* past_v = (const float*)d_in[2];
    const float* W_attn = (const float*)d_in[3];
    const float* b_attn = (const float*)d_in[4];
    const float* W_proj = (const float*)d_in[5];
    const float* b_proj = (const float*)d_in[6];

    float* out  = (float*)d_out;
    float* outk = out + OUT_K_OFF;
    float* outv = out + OUT_V_OFF;

    int dev = 0, nsm = 148;
    cudaGetDevice(&dev);
    cudaDeviceGetAttribute(&nsm, cudaDevAttrMultiProcessorCount, dev);

    // host-side attribute set — not a stream op, capture-safe
    cudaFuncSetAttribute(attn_kernel, cudaFuncAttributeMaxDynamicSharedMemorySize,
                         ATTN_SMEM);

    // 1) QKV projection (split-K): partials -> reduce -> g_q + out k/v tails
    gemm_partial<0><<<dim3(48, 2, KSPLIT), 256>>>(x, W_attn);
    gemm_reduce<0><<<384, 256>>>(b_attn, nullptr, outk, outv);

    // 2) persistent fused KV-copy + attention, then deterministic combine
    attn_kernel<<<2 * nsm, 256, ATTN_SMEM>>>(past_k, past_v, outk, outv);
    combine_kernel<<<256, 128>>>();

    // 3) output projection (split-K)
    gemm_partial<1><<<dim3(16, 2, KSPLIT), 256>>>(nullptr, W_proj);
    gemm_reduce<1><<<128, 256>>>(b_proj, out, nullptr, nullptr);
}